// round 8
// baseline (speedup 1.0000x reference)
#include <cuda_runtime.h>
#include <cuda_bf16.h>
#include <cuda_fp16.h>

// Fused separable 15x15 Gaussian blur, fp32 in/out, N x 1024 x 1024.
// R7: horizontal pass goes packed. Items of 8 outputs; 4 packed f32x2
//  accumulators (o0,o1)(o2,o3)(o4,o5)(o6,o7). Tap j -> acc b consumes pair
//  (v[s],v[s+1]) with s=2b+1+j: even-s pairs are the free aligned register
//  pairs of the LDG.128 chunks; 11 odd-s pairs cost movs, reused ~4x each.
//  60 FFMA2 + ~22 movs per 8 px (vs 120 FFMA). 6 LDG.128 per 8 px.
// Phase 2 unchanged from R6 (fp16 hz, LDS.32 half2 -> FFMA2 fp32).

#define RAD 7
#define KS  15
#define TX  128
#define TY  32
#define HYP 48                  // 46 needed rows padded to 48 (3 iters x 16 rows)
#define NTHREADS 256
#define IMG_W 1024
#define IMG_H 1024

typedef unsigned long long ull;

__device__ __forceinline__ ull pack2(float a, float b) {
    ull r;
    asm("mov.b64 %0, {%1, %2};" : "=l"(r) : "f"(a), "f"(b));
    return r;
}
__device__ __forceinline__ void unpack2(ull p, float& a, float& b) {
    asm("mov.b64 {%0, %1}, %2;" : "=f"(a), "=f"(b) : "l"(p));
}
__device__ __forceinline__ ull ffma2(ull a, ull b, ull c) {
    ull d;
    asm("fma.rn.f32x2 %0, %1, %2, %3;" : "=l"(d) : "l"(a), "l"(b), "l"(c));
    return d;
}
__device__ __forceinline__ ull fmul2(ull a, ull b) {
    ull d;
    asm("mul.rn.f32x2 %0, %1, %2;" : "=l"(d) : "l"(a), "l"(b));
    return d;
}
// half2 (as u32) -> packed f32x2 in one 64-bit reg
__device__ __forceinline__ ull h2_to_f2(unsigned int h) {
    float lo, hi;
    asm("{.reg .f16 l, h;\n\t"
        " mov.b32 {l, h}, %2;\n\t"
        " cvt.f32.f16 %0, l;\n\t"
        " cvt.f32.f16 %1, h;}"
        : "=f"(lo), "=f"(hi) : "r"(h));
    return pack2(lo, hi);
}

__global__ void __launch_bounds__(NTHREADS, 4)
gauss15_fused7_kernel(const float* __restrict__ x,
                      const float* __restrict__ sigma_p,
                      const float* __restrict__ gain_p,
                      float* __restrict__ out)
{
    __shared__ alignas(16) __half s_hz[HYP * TX];   // 12 KB

    const int tid = threadIdx.x;
    const int x0 = blockIdx.x * TX;
    const int y0 = blockIdx.y * TY;
    const long long plane = (long long)blockIdx.z * (IMG_W * IMG_H);
    const float* img = x + plane;
    float* outp = out + plane;

    // ---- weights: 8 distinct scalars, then broadcast f32x2 pairs ----
    const float s = fabsf(sigma_p[0]);
    const float g = gain_p[0];
    const float inv2s2 = 1.0f / (2.0f * s * s);
    ull wv[8];
#pragma unroll
    for (int j = 0; j < 8; j++) {
        float d = (float)(j - RAD);
        float w = __expf(-d * d * inv2s2);
        wv[j] = pack2(w, w);
    }
#define WV(j) wv[((j) <= 7) ? (j) : (14 - (j))]

    // ---- phase 1: horizontal conv, 8 outputs/item, packed f32x2 ----
    // cg = tid & 15 (item col-group: cols x0+8cg .. +7), r = (tid>>4) + 16*it.
    // window v[0..23] = in[W + m], W = x0 + 8cg - 8. o_a = sum_j w[j] v[a+1+j].
    {
        const int cg = tid & 15;
        const int r0 = tid >> 4;
        const int gxb = x0 + 8 * cg - 8;
        const float* rowp0 = img + (long long)(y0 - RAD + r0) * IMG_W + gxb;
        __half* hzp0 = s_hz + r0 * TX + cg * 8;

        bool cvx[6];
#pragma unroll
        for (int k = 0; k < 6; k++) {
            int gx = gxb + 4 * k;
            cvx[k] = (gx >= 0) && (gx < IMG_W);
        }

#pragma unroll
        for (int it = 0; it < 3; it++) {
            const int gy = y0 - RAD + (r0 + 16 * it);
            const bool rv = ((unsigned)gy < (unsigned)IMG_H);
            const float* rowp = rowp0 + (long long)(16 * it) * IMG_W;

            float v[24];
#pragma unroll
            for (int k = 0; k < 6; k++) {
                float4 t = make_float4(0.f, 0.f, 0.f, 0.f);
                if (rv && cvx[k]) t = *(const float4*)(rowp + 4 * k);
                v[4 * k + 0] = t.x; v[4 * k + 1] = t.y;
                v[4 * k + 2] = t.z; v[4 * k + 3] = t.w;
            }

            ull A[4] = {0ull, 0ull, 0ull, 0ull};
            // pair start s = 2b+1+j, s in [1,21]; even s = free aligned pair
#pragma unroll
            for (int s2 = 1; s2 <= 21; s2++) {
                ull p = pack2(v[s2], v[s2 + 1]);
#pragma unroll
                for (int b = 0; b < 4; b++) {
                    int j = s2 - 1 - 2 * b;
                    if (j >= 0 && j <= 14)
                        A[b] = ffma2(WV(j), p, A[b]);
                }
            }

            // 4 packed accs -> 4 half2 -> one STS.128
            uint4 st;
            {
                float a0, a1; unpack2(A[0], a0, a1);
                __half2 h = __floats2half2_rn(a0, a1);
                st.x = *(unsigned int*)&h;
            }
            {
                float a0, a1; unpack2(A[1], a0, a1);
                __half2 h = __floats2half2_rn(a0, a1);
                st.y = *(unsigned int*)&h;
            }
            {
                float a0, a1; unpack2(A[2], a0, a1);
                __half2 h = __floats2half2_rn(a0, a1);
                st.z = *(unsigned int*)&h;
            }
            {
                float a0, a1; unpack2(A[3], a0, a1);
                __half2 h = __floats2half2_rn(a0, a1);
                st.w = *(unsigned int*)&h;
            }
            *(uint4*)(hzp0 + 16 * it * TX) = st;
        }
    }
    __syncthreads();

    // ---- phase 2: vertical conv, 4 strips x 8 rows x 64 col-pairs ----
    {
        const int cp = tid & 63;
        const int ss = tid >> 6;
        const int ob = ss * 8;

        ull acc[8];
#pragma unroll
        for (int i = 0; i < 8; i++) acc[i] = 0ull;

        const unsigned int* hzbase =
            (const unsigned int*)(s_hz + ob * TX) + cp;   // half2 units, row stride TX/2
#pragma unroll
        for (int t = 0; t < KS + 7; t++) {                // hz rows ob .. ob+21
            ull v = h2_to_f2(hzbase[t * (TX / 2)]);
#pragma unroll
            for (int k = 0; k < 8; k++) {
                if (t >= k && t - k < KS)
                    acc[k] = ffma2(WV(t - k), v, acc[k]);
            }
        }

        const ull gp = pack2(g, g);
        float* o = outp + (long long)(y0 + ob) * IMG_W + x0 + cp * 2;
#pragma unroll
        for (int k = 0; k < 8; k++) {
            ull r = fmul2(acc[k], gp);
            float a, b;
            unpack2(r, a, b);
            *(float2*)(o + (long long)k * IMG_W) = make_float2(a, b);
        }
    }
}

extern "C" void kernel_launch(void* const* d_in, const int* in_sizes, int n_in,
                              void* d_out, int out_size)
{
    const float* x     = (const float*)d_in[0];
    const float* sigma = (const float*)d_in[1];
    const float* gain  = (const float*)d_in[2];
    float* out = (float*)d_out;

    int nimg = in_sizes[0] / (IMG_W * IMG_H);

    dim3 grid(IMG_W / TX, IMG_H / TY, nimg);
    gauss15_fused7_kernel<<<grid, NTHREADS>>>(x, sigma, gain, out);
}

// round 9
// speedup vs baseline: 1.0051x; 1.0051x over previous
#include <cuda_runtime.h>
#include <cuda_bf16.h>
#include <cuda_fp16.h>

// Fused separable 15x15 Gaussian blur, fp32 in/out, N x 1024 x 1024.
// R8: TY=64 (y-halo 1.25x instead of 1.5x), 256 threads, occ-5 target.
//  Phase 1: horizontal conv direct from global (5 predicated LDG.128 per
//           4-output item, scalar FFMA), f32 results, one STS.128.
//  Phase 2: vertical conv; hz rows read as ld.shared.b64 float2 straight
//           into fma.rn.f32x2 operands (no cvt, no packing movs).
//           2 serial 8-row strips per thread, 64 col-pairs, all active.

#define RAD 7
#define KS  15
#define TX  128
#define TY  64
#define HYP 80                  // 78 needed rows padded to 80 (10 iters x 8 rows)
#define NTHREADS 256
#define IMG_W 1024
#define IMG_H 1024

typedef unsigned long long ull;

__device__ __forceinline__ ull pack2(float a, float b) {
    ull r;
    asm("mov.b64 %0, {%1, %2};" : "=l"(r) : "f"(a), "f"(b));
    return r;
}
__device__ __forceinline__ void unpack2(ull p, float& a, float& b) {
    asm("mov.b64 {%0, %1}, %2;" : "=f"(a), "=f"(b) : "l"(p));
}
__device__ __forceinline__ ull ffma2(ull a, ull b, ull c) {
    ull d;
    asm("fma.rn.f32x2 %0, %1, %2, %3;" : "=l"(d) : "l"(a), "l"(b), "l"(c));
    return d;
}
__device__ __forceinline__ ull fmul2(ull a, ull b) {
    ull d;
    asm("mul.rn.f32x2 %0, %1, %2;" : "=l"(d) : "l"(a), "l"(b));
    return d;
}

__global__ void __launch_bounds__(NTHREADS, 5)
gauss15_fused8_kernel(const float* __restrict__ x,
                      const float* __restrict__ sigma_p,
                      const float* __restrict__ gain_p,
                      float* __restrict__ out)
{
    __shared__ alignas(16) float s_hz[HYP * TX];   // 40 KB

    const int tid = threadIdx.x;
    const int x0 = blockIdx.x * TX;
    const int y0 = blockIdx.y * TY;
    const long long plane = (long long)blockIdx.z * (IMG_W * IMG_H);
    const float* img = x + plane;
    float* outp = out + plane;

    // ---- weights: 8 distinct scalars (symmetric) ----
    const float s = fabsf(sigma_p[0]);
    const float g = gain_p[0];
    const float inv2s2 = 1.0f / (2.0f * s * s);
    float ws[8];
#pragma unroll
    for (int j = 0; j < 8; j++) {
        float d = (float)(j - RAD);
        ws[j] = __expf(-d * d * inv2s2);
    }
#define WJ(j) ws[((j) <= 7) ? (j) : (14 - (j))]

    // ---- phase 1: horizontal conv, direct from global ----
    // cg = tid & 31 (invariant), r = (tid>>5) + 8*it, it in [0,10).
    {
        const int cg = tid & 31;
        const int r0 = tid >> 5;
        const int gxb = x0 - 8 + cg * 4;
        const float* rowp0 = img + (long long)(y0 - RAD + r0) * IMG_W + gxb;
        float* hzp0 = s_hz + r0 * TX + cg * 4;

        bool cvx[5];
#pragma unroll
        for (int k = 0; k < 5; k++) {
            int gx = gxb + 4 * k;
            cvx[k] = (gx >= 0) && (gx < IMG_W);
        }

#pragma unroll
        for (int it = 0; it < 10; it++) {
            const int gy = y0 - RAD + (r0 + 8 * it);
            const bool rv = ((unsigned)gy < (unsigned)IMG_H);
            const float* rowp = rowp0 + (long long)(8 * it) * IMG_W;

            float v[20];
#pragma unroll
            for (int k = 0; k < 5; k++) {
                float4 t = make_float4(0.f, 0.f, 0.f, 0.f);
                if (rv && cvx[k]) t = *(const float4*)(rowp + 4 * k);
                v[4 * k + 0] = t.x; v[4 * k + 1] = t.y;
                v[4 * k + 2] = t.z; v[4 * k + 3] = t.w;
            }
            float o0 = 0.f, o1 = 0.f, o2 = 0.f, o3 = 0.f;
#pragma unroll
            for (int j = 0; j < KS; j++) {
                float wj = WJ(j);
                o0 = fmaf(wj, v[1 + j], o0);
                o1 = fmaf(wj, v[2 + j], o1);
                o2 = fmaf(wj, v[3 + j], o2);
                o3 = fmaf(wj, v[4 + j], o3);
            }
            *(float4*)(hzp0 + 8 * it * TX) = make_float4(o0, o1, o2, o3);
        }
    }
    __syncthreads();

    // ---- phase 2: vertical conv; 8 strips x 8 rows x 64 col-pairs ----
    // cp = tid & 63 (cols 2cp, 2cp+1), base strip ss0 = tid >> 6 in [0,4);
    // each thread does strips ss0 and ss0+4 serially.
    {
        const int cp = tid & 63;
        const int ss0 = tid >> 6;

        ull wv[8];
#pragma unroll
        for (int j = 0; j < 8; j++) wv[j] = pack2(ws[j], ws[j]);
#define WV(j) wv[((j) <= 7) ? (j) : (14 - (j))]
        const ull gp = pack2(g, g);

#pragma unroll
        for (int sit = 0; sit < 2; sit++) {
            const int ob = (ss0 + 4 * sit) * 8;

            ull acc[8];
#pragma unroll
            for (int i = 0; i < 8; i++) acc[i] = 0ull;

            // row stride in ull units: TX floats = TX/2 ull
            const ull* hzbase = (const ull*)(s_hz + ob * TX) + cp;
#pragma unroll
            for (int t = 0; t < KS + 7; t++) {            // hz rows ob .. ob+21
                ull v = hzbase[t * (TX / 2)];
#pragma unroll
                for (int k = 0; k < 8; k++) {
                    if (t >= k && t - k < KS)
                        acc[k] = ffma2(WV(t - k), v, acc[k]);
                }
            }

            float* o = outp + (long long)(y0 + ob) * IMG_W + x0 + cp * 2;
#pragma unroll
            for (int k = 0; k < 8; k++) {
                ull r = fmul2(acc[k], gp);
                float a, b;
                unpack2(r, a, b);
                *(float2*)(o + (long long)k * IMG_W) = make_float2(a, b);
            }
        }
    }
}

extern "C" void kernel_launch(void* const* d_in, const int* in_sizes, int n_in,
                              void* d_out, int out_size)
{
    const float* x     = (const float*)d_in[0];
    const float* sigma = (const float*)d_in[1];
    const float* gain  = (const float*)d_in[2];
    float* out = (float*)d_out;

    int nimg = in_sizes[0] / (IMG_W * IMG_H);

    dim3 grid(IMG_W / TX, IMG_H / TY, nimg);
    gauss15_fused8_kernel<<<grid, NTHREADS>>>(x, sigma, gain, out);
}

// round 10
// speedup vs baseline: 1.0491x; 1.0437x over previous
#include <cuda_runtime.h>
#include <cuda_bf16.h>

// Fused separable 15x15 Gaussian blur, fp32 in/out, N x 1024 x 1024.
// R9: L1-wavefront reduction round.
//  Phase 1: 8 outputs per item, scalar FFMA (no packing movs).
//           6 predicated LDG.128 per 8 px -> 12B/px through L1 (was 20).
//           Two STS.128 per item, f32 intermediate.
//  Phase 2: 16-row strips x 64 col-pairs (256 threads, 1 strip each).
//           30 ld.shared.b64 per 32 px (amp 1.875x, was 2.75x), float2
//           straight into fma.rn.f32x2, 16 STG.64 per thread.
// Tile 128x64, 256 threads, 2048 blocks.

#define RAD 7
#define KS  15
#define TX  128
#define TY  64
#define HYP 80                  // 78 needed rows padded to 80 (5 iters x 16 rows)
#define NTHREADS 256
#define IMG_W 1024
#define IMG_H 1024

typedef unsigned long long ull;

__device__ __forceinline__ ull pack2(float a, float b) {
    ull r;
    asm("mov.b64 %0, {%1, %2};" : "=l"(r) : "f"(a), "f"(b));
    return r;
}
__device__ __forceinline__ void unpack2(ull p, float& a, float& b) {
    asm("mov.b64 {%0, %1}, %2;" : "=f"(a), "=f"(b) : "l"(p));
}
__device__ __forceinline__ ull ffma2(ull a, ull b, ull c) {
    ull d;
    asm("fma.rn.f32x2 %0, %1, %2, %3;" : "=l"(d) : "l"(a), "l"(b), "l"(c));
    return d;
}
__device__ __forceinline__ ull fmul2(ull a, ull b) {
    ull d;
    asm("mul.rn.f32x2 %0, %1, %2;" : "=l"(d) : "l"(a), "l"(b));
    return d;
}

__global__ void __launch_bounds__(NTHREADS, 4)
gauss15_fused9_kernel(const float* __restrict__ x,
                      const float* __restrict__ sigma_p,
                      const float* __restrict__ gain_p,
                      float* __restrict__ out)
{
    __shared__ alignas(16) float s_hz[HYP * TX];   // 40 KB

    const int tid = threadIdx.x;
    const int x0 = blockIdx.x * TX;
    const int y0 = blockIdx.y * TY;
    const long long plane = (long long)blockIdx.z * (IMG_W * IMG_H);
    const float* img = x + plane;
    float* outp = out + plane;

    // ---- weights: 8 distinct scalars (symmetric) ----
    const float s = fabsf(sigma_p[0]);
    const float g = gain_p[0];
    const float inv2s2 = 1.0f / (2.0f * s * s);
    float ws[8];
#pragma unroll
    for (int j = 0; j < 8; j++) {
        float d = (float)(j - RAD);
        ws[j] = __expf(-d * d * inv2s2);
    }
#define WJ(j) ws[((j) <= 7) ? (j) : (14 - (j))]

    // ---- phase 1: horizontal conv, 8 outputs/item, scalar FFMA ----
    // cg = tid & 15 (cols x0+8cg..+7), r = (tid>>4) + 16*it, it in [0,5).
    // window v[0..23] = in[gxb + m], gxb = x0 + 8cg - 8; o_a = sum_j w[j] v[a+1+j].
    {
        const int cg = tid & 15;
        const int r0 = tid >> 4;
        const int gxb = x0 + 8 * cg - 8;
        const float* rowp0 = img + (long long)(y0 - RAD + r0) * IMG_W + gxb;
        float* hzp0 = s_hz + r0 * TX + cg * 8;

        bool cvx[6];
#pragma unroll
        for (int k = 0; k < 6; k++) {
            int gx = gxb + 4 * k;
            cvx[k] = (gx >= 0) && (gx < IMG_W);
        }

#pragma unroll
        for (int it = 0; it < 5; it++) {
            const int gy = y0 - RAD + (r0 + 16 * it);
            const bool rv = ((unsigned)gy < (unsigned)IMG_H);
            const float* rowp = rowp0 + (long long)(16 * it) * IMG_W;

            float v[24];
#pragma unroll
            for (int k = 0; k < 6; k++) {
                float4 t = make_float4(0.f, 0.f, 0.f, 0.f);
                if (rv && cvx[k]) t = *(const float4*)(rowp + 4 * k);
                v[4 * k + 0] = t.x; v[4 * k + 1] = t.y;
                v[4 * k + 2] = t.z; v[4 * k + 3] = t.w;
            }

            float o[8];
#pragma unroll
            for (int a = 0; a < 8; a++) o[a] = 0.f;
#pragma unroll
            for (int j = 0; j < KS; j++) {
                float wj = WJ(j);
#pragma unroll
                for (int a = 0; a < 8; a++)
                    o[a] = fmaf(wj, v[a + 1 + j], o[a]);
            }

            float* hzp = hzp0 + 16 * it * TX;
            *(float4*)(hzp + 0) = make_float4(o[0], o[1], o[2], o[3]);
            *(float4*)(hzp + 4) = make_float4(o[4], o[5], o[6], o[7]);
        }
    }
    __syncthreads();

    // ---- phase 2: vertical conv, 4 strips x 16 rows x 64 col-pairs ----
    // cp = tid & 63 (cols 2cp, 2cp+1), ss = tid >> 6 in [0,4), ob = 16*ss.
    {
        const int cp = tid & 63;
        const int ss = tid >> 6;
        const int ob = ss * 16;

        ull wv[8];
#pragma unroll
        for (int j = 0; j < 8; j++) wv[j] = pack2(ws[j], ws[j]);
#define WV(j) wv[((j) <= 7) ? (j) : (14 - (j))]
        const ull gp = pack2(g, g);

        ull acc[16];
#pragma unroll
        for (int i = 0; i < 16; i++) acc[i] = 0ull;

        // row stride in ull units: TX floats = TX/2 ull
        const ull* hzbase = (const ull*)(s_hz + ob * TX) + cp;
#pragma unroll
        for (int t = 0; t < KS + 15; t++) {               // hz rows ob .. ob+29
            ull v = hzbase[t * (TX / 2)];
#pragma unroll
            for (int k = 0; k < 16; k++) {
                if (t >= k && t - k < KS)
                    acc[k] = ffma2(WV(t - k), v, acc[k]);
            }
        }

        float* o = outp + (long long)(y0 + ob) * IMG_W + x0 + cp * 2;
#pragma unroll
        for (int k = 0; k < 16; k++) {
            ull r = fmul2(acc[k], gp);
            float a, b;
            unpack2(r, a, b);
            *(float2*)(o + (long long)k * IMG_W) = make_float2(a, b);
        }
    }
}

extern "C" void kernel_launch(void* const* d_in, const int* in_sizes, int n_in,
                              void* d_out, int out_size)
{
    const float* x     = (const float*)d_in[0];
    const float* sigma = (const float*)d_in[1];
    const float* gain  = (const float*)d_in[2];
    float* out = (float*)d_out;

    int nimg = in_sizes[0] / (IMG_W * IMG_H);

    dim3 grid(IMG_W / TX, IMG_H / TY, nimg);
    gauss15_fused9_kernel<<<grid, NTHREADS>>>(x, sigma, gain, out);
}